// round 11
// baseline (speedup 1.0000x reference)
#include <cuda_runtime.h>
#include <cstdint>

#define BB 4
#define SS 4096
#define EE 1024
#define DD 64
#define TK 32
#define NT (SS / TK)      // 128 key tiles total
#define NSPLIT 64         // tiles per k-split

// ---------------- device scratch ----------------
__device__ uint32_t g_Qh[BB * SS * DD / 2];   // [s][d] hi pairs (truncated)
__device__ uint32_t g_Ql[BB * SS * DD / 2];   // [s][d] lo pairs
__device__ uint32_t g_K [BB * SS * DD / 2];   // [s][d] rounded bf16 pairs
__device__ uint32_t g_Vh[BB * DD * SS / 2];   // [d][s] hi (V^T)
__device__ uint32_t g_Vl[BB * DD * SS / 2];   // [d][s] lo
__device__ uint32_t g_Mb[BB * SS * (SS / 32)];  // bit-packed mask, 8MB

// ---------------- helpers ----------------
__device__ __forceinline__ uint32_t hip(float a, float b) {
    return __byte_perm(__float_as_uint(a), __float_as_uint(b), 0x7632);
}
__device__ __forceinline__ float lof(float a) {
    return a - __uint_as_float(__float_as_uint(a) & 0xFFFF0000u);
}
__device__ __forceinline__ uint32_t lop(float a, float b) {
    uint32_t r;
    asm("cvt.rn.bf16x2.f32 %0, %1, %2;" : "=r"(r) : "f"(lof(b)), "f"(lof(a)));
    return r;
}
__device__ __forceinline__ uint32_t rnp(float a, float b) {   // rounded pair
    uint32_t r;
    asm("cvt.rn.bf16x2.f32 %0, %1, %2;" : "=r"(r) : "f"(b), "f"(a));
    return r;
}
__device__ __forceinline__ unsigned short f2bf(float f) {
    unsigned short u; asm("cvt.rn.bf16.f32 %0, %1;" : "=h"(u) : "f"(f)); return u;
}
__device__ __forceinline__ void mma16816(float4& c, const uint32_t a[4],
                                         uint32_t b0, uint32_t b1) {
    asm volatile(
        "mma.sync.aligned.m16n8k16.row.col.f32.bf16.bf16.f32 "
        "{%0,%1,%2,%3}, {%4,%5,%6,%7}, {%8,%9}, {%0,%1,%2,%3};"
        : "+f"(c.x), "+f"(c.y), "+f"(c.z), "+f"(c.w)
        : "r"(a[0]), "r"(a[1]), "r"(a[2]), "r"(a[3]), "r"(b0), "r"(b1));
}
__device__ __forceinline__ uint32_t smem_u32(const void* p) {
    uint32_t a;
    asm("{ .reg .u64 t; cvta.to.shared.u64 t, %1; cvt.u32.u64 %0, t; }" : "=r"(a) : "l"(p));
    return a;
}
__device__ __forceinline__ void cpa(uint32_t dst, const void* src) {
    asm volatile("cp.async.cg.shared.global [%0], [%1], 16;" :: "r"(dst), "l"(src));
}
#define CP_COMMIT() asm volatile("cp.async.commit_group;" ::: "memory")
#define CP_WAIT1()  asm volatile("cp.async.wait_group 1;" ::: "memory")
#define BARP(id)    asm volatile("bar.sync %0, 64;" :: "r"(id) : "memory")

#define RSTRIDE 144   // proj smem row stride

// ---------------------------------------------------------------------------
// Fused prep kernel (896 CTAs x 256 thr), pack CTAs FIRST for overlap:
//   bx in [0,512)   : mask bit-pack (DRAM-bound)
//   bx in [512,896) : projection with register double-buffered W and X.
//                     py = (bx-512)/128: 0=Q hi/lo, 1=K rn, 2=V^T hi/lo
// ---------------------------------------------------------------------------
__global__ __launch_bounds__(256) void prep_kernel(
    const float* __restrict__ Xq, const float* __restrict__ Xk,
    const float* __restrict__ Xv,
    const float* __restrict__ Wq, const float* __restrict__ Wk,
    const float* __restrict__ Wv, const int* __restrict__ mask)
{
    const int tid = threadIdx.x;
    const int w = tid >> 5, l = tid & 31;

    if (blockIdx.x < 512) {
        // ---- mask bit-pack: 2M words over 512 CTAs x 8 warps ----
        const int gw = blockIdx.x * 8 + w;             // 0..4095
        #pragma unroll 4
        for (int it = 0; it < 16; it++) {
            size_t wbase = (size_t)gw * 512 + it * 32;
            size_t ibase = wbase * 32;
            int v[32];
            #pragma unroll
            for (int j = 0; j < 32; j++) v[j] = mask[ibase + j * 32 + l];
            uint32_t myw = 0;
            #pragma unroll
            for (int j = 0; j < 32; j++) {
                uint32_t bt = __ballot_sync(0xFFFFFFFFu, v[j] != 0);
                if (l == j) myw = bt;
            }
            g_Mb[wbase + l] = myw;
        }
        return;
    }

    const int px = (blockIdx.x - 512) & 127;
    const int py = (blockIdx.x - 512) >> 7;   // 0,1,2

    const float* __restrict__ X;
    const float* __restrict__ W;
    if (py == 0)      { X = Xq; W = Wq; }
    else if (py == 1) { X = Xk; W = Wk; }
    else              { X = Xv; W = Wv; }

    __shared__ __align__(16) char sWh[64 * RSTRIDE];
    __shared__ __align__(16) char sWl[64 * RSTRIDE];

    const int gr = l >> 2, lq = l & 3;
    const int r0 = px * 128;
    const float* Xbase = X + (size_t)(r0 + w * 16) * EE;

    float4 C[8];
    #pragma unroll
    for (int n = 0; n < 8; n++) C[n] = make_float4(0.f, 0.f, 0.f, 0.f);

    // register double buffers for W tile and X fragments
    float4 wv[4];
    float2 xv[16];
    #pragma unroll
    for (int i = 0; i < 4; i++) {
        int idx = tid + i * 256;
        int d = idx >> 4, c4 = idx & 15;
        wv[i] = *(const float4*)&W[(size_t)d * EE + c4 * 4];
    }
    #pragma unroll
    for (int kc = 0; kc < 4; kc++) {
        xv[kc * 4 + 0] = *(const float2*)&Xbase[gr * EE + lq * 2 + kc * 16];
        xv[kc * 4 + 1] = *(const float2*)&Xbase[(gr + 8) * EE + lq * 2 + kc * 16];
        xv[kc * 4 + 2] = *(const float2*)&Xbase[gr * EE + lq * 2 + kc * 16 + 8];
        xv[kc * 4 + 3] = *(const float2*)&Xbase[(gr + 8) * EE + lq * 2 + kc * 16 + 8];
    }

    for (int e0 = 0; e0 < EE; e0 += 64) {
        __syncthreads();
        #pragma unroll
        for (int i = 0; i < 4; i++) {
            int idx = tid + i * 256;
            int d = idx >> 4, c4 = idx & 15;
            *(uint2*)(sWh + d * RSTRIDE + c4 * 8) =
                make_uint2(hip(wv[i].x, wv[i].y), hip(wv[i].z, wv[i].w));
            *(uint2*)(sWl + d * RSTRIDE + c4 * 8) =
                make_uint2(lop(wv[i].x, wv[i].y), lop(wv[i].z, wv[i].w));
        }
        __syncthreads();

        // prefetch next tile (W + X) while computing this one
        float4 wn[4];
        float2 xn[16];
        if (e0 + 64 < EE) {
            const int e1 = e0 + 64;
            #pragma unroll
            for (int i = 0; i < 4; i++) {
                int idx = tid + i * 256;
                int d = idx >> 4, c4 = idx & 15;
                wn[i] = *(const float4*)&W[(size_t)d * EE + e1 + c4 * 4];
            }
            const float* Xw = Xbase + e1;
            #pragma unroll
            for (int kc = 0; kc < 4; kc++) {
                xn[kc * 4 + 0] = *(const float2*)&Xw[gr * EE + lq * 2 + kc * 16];
                xn[kc * 4 + 1] = *(const float2*)&Xw[(gr + 8) * EE + lq * 2 + kc * 16];
                xn[kc * 4 + 2] = *(const float2*)&Xw[gr * EE + lq * 2 + kc * 16 + 8];
                xn[kc * 4 + 3] = *(const float2*)&Xw[(gr + 8) * EE + lq * 2 + kc * 16 + 8];
            }
        }

        #pragma unroll
        for (int kc = 0; kc < 4; kc++) {
            float2 x00 = xv[kc * 4 + 0], x10 = xv[kc * 4 + 1];
            float2 x01 = xv[kc * 4 + 2], x11 = xv[kc * 4 + 3];
            uint32_t Ah[4] = {hip(x00.x, x00.y), hip(x10.x, x10.y),
                              hip(x01.x, x01.y), hip(x11.x, x11.y)};
            uint32_t Al[4] = {lop(x00.x, x00.y), lop(x10.x, x10.y),
                              lop(x01.x, x01.y), lop(x11.x, x11.y)};
            #pragma unroll
            for (int n = 0; n < 8; n++) {
                const char* bh = sWh + (n * 8 + gr) * RSTRIDE + (lq + kc * 8) * 4;
                const char* bl = sWl + (n * 8 + gr) * RSTRIDE + (lq + kc * 8) * 4;
                uint32_t bh0 = *(const uint32_t*)bh;
                uint32_t bh1 = *(const uint32_t*)(bh + 16);
                uint32_t bl0 = *(const uint32_t*)bl;
                uint32_t bl1 = *(const uint32_t*)(bl + 16);
                mma16816(C[n], Ah, bh0, bh1);
                mma16816(C[n], Al, bh0, bh1);
                mma16816(C[n], Ah, bl0, bl1);
            }
        }

        #pragma unroll
        for (int i = 0; i < 4; i++) wv[i] = wn[i];
        #pragma unroll
        for (int i = 0; i < 16; i++) xv[i] = xn[i];
    }

    const int r = r0 + w * 16 + gr;
    if (py == 0) {
        #pragma unroll
        for (int n = 0; n < 8; n++) {
            int d2 = n * 4 + lq;
            g_Qh[(size_t)r * 32 + d2]       = hip(C[n].x, C[n].y);
            g_Ql[(size_t)r * 32 + d2]       = lop(C[n].x, C[n].y);
            g_Qh[(size_t)(r + 8) * 32 + d2] = hip(C[n].z, C[n].w);
            g_Ql[(size_t)(r + 8) * 32 + d2] = lop(C[n].z, C[n].w);
        }
    } else if (py == 1) {
        #pragma unroll
        for (int n = 0; n < 8; n++) {
            int d2 = n * 4 + lq;
            g_K[(size_t)r * 32 + d2]       = rnp(C[n].x, C[n].y);
            g_K[(size_t)(r + 8) * 32 + d2] = rnp(C[n].z, C[n].w);
        }
    } else {
        unsigned short* Vh16 = (unsigned short*)g_Vh;
        unsigned short* Vl16 = (unsigned short*)g_Vl;
        const int bi = r >> 12, s = r & 4095;
        #pragma unroll
        for (int n = 0; n < 8; n++) {
            int d = n * 8 + lq * 2;
            size_t o0 = (size_t)(bi * DD + d) * SS + s;
            size_t o1 = (size_t)(bi * DD + d + 1) * SS + s;
            Vh16[o0]     = (unsigned short)(__float_as_uint(C[n].x) >> 16);
            Vl16[o0]     = f2bf(lof(C[n].x));
            Vh16[o1]     = (unsigned short)(__float_as_uint(C[n].y) >> 16);
            Vl16[o1]     = f2bf(lof(C[n].y));
            Vh16[o0 + 8] = (unsigned short)(__float_as_uint(C[n].z) >> 16);
            Vl16[o0 + 8] = f2bf(lof(C[n].z));
            Vh16[o1 + 8] = (unsigned short)(__float_as_uint(C[n].w) >> 16);
            Vl16[o1 + 8] = f2bf(lof(C[n].w));
        }
    }
}

// ---------------------------------------------------------------------------
// Attention with intra-CTA split-K: 128 thr / 4 warps / 32 q rows.
// Warp-pair p owns k-tiles [p*64, p*64+64) with its own double buffer,
// cp.async groups, and named barrier. Buffer: K 4KB | Vh 4KB | Vl 4KB.
// 4 CTAs/SM (smem 48KB) -> all 512 CTAs in one wave.
// Shared-memory fragment loads are plain C++ (compiler-schedulable, MLP);
// BARP's memory clobber orders them against cp.async completion.
// ---------------------------------------------------------------------------
__device__ __forceinline__ void stage_tile(
    uint32_t base, int ptid, int t,
    const uint4* Kg, const uint4* Vhg, const uint4* Vlg)
{
    const int k0 = t * TK;
    #pragma unroll
    for (int j = 0; j < 4; j++) {       // K: 32 rows x 8 chunks (4KB)
        int idx = ptid + j * 64;
        int r = idx >> 3, c = idx & 7;
        uint32_t d = base + r * 128 + ((c ^ (r & 7)) << 4);
        cpa(d, Kg + (size_t)(k0 + r) * 8 + c);
    }
    #pragma unroll
    for (int j = 0; j < 4; j++) {       // V^T: 64 rows x 4 chunks (4KB each)
        int idx = ptid + j * 64;
        int r = idx >> 2, c = idx & 3;
        uint32_t d = base + 4096 + r * 64 + ((c ^ ((r >> 1) & 3)) << 4);
        cpa(d,        Vhg + (size_t)r * 512 + (k0 >> 3) + c);
        cpa(d + 4096, Vlg + (size_t)r * 512 + (k0 >> 3) + c);
    }
}

__global__ __launch_bounds__(128, 4) void attn_kernel(float* __restrict__ out)
{
    __shared__ __align__(16) char sm[49152];

    const int tid = threadIdx.x;
    const int w = tid >> 5, l = tid & 31;
    const int gr = l >> 2, lq = l & 3;
    const int split = w >> 1, sub = w & 1;
    const int ptid = tid & 63;
    const int b = blockIdx.y;
    const int qloc = sub * 16 + gr;
    const int qr = blockIdx.x * 32 + qloc;

    const uint32_t pbase = smem_u32(sm) + split * 24576;
    const char* psm = sm + split * 24576;

    // Q fragments
    uint32_t Ah[4][4], Al[4][4];
    {
        const uint32_t* Qhp = g_Qh + (size_t)b * SS * 32;
        const uint32_t* Qlp = g_Ql + (size_t)b * SS * 32;
        #pragma unroll
        for (int kc = 0; kc < 4; kc++) {
            int c0 = lq + kc * 8;
            Ah[kc][0] = Qhp[(size_t)qr * 32 + c0];
            Ah[kc][1] = Qhp[(size_t)(qr + 8) * 32 + c0];
            Ah[kc][2] = Qhp[(size_t)qr * 32 + c0 + 4];
            Ah[kc][3] = Qhp[(size_t)(qr + 8) * 32 + c0 + 4];
            Al[kc][0] = Qlp[(size_t)qr * 32 + c0];
            Al[kc][1] = Qlp[(size_t)(qr + 8) * 32 + c0];
            Al[kc][2] = Qlp[(size_t)qr * 32 + c0 + 4];
            Al[kc][3] = Qlp[(size_t)(qr + 8) * 32 + c0 + 4];
        }
    }

    float4 O[8];
    #pragma unroll
    for (int n = 0; n < 8; n++) O[n] = make_float4(0.f, 0.f, 0.f, 0.f);
    float l0 = 0.f, l1 = 0.f;

    const uint32_t* M0 = g_Mb + (size_t)(b * SS + qr) * NT + split * NSPLIT;
    const uint32_t* M1 = M0 + (size_t)8 * NT;
    const uint4* Kg  = (const uint4*)g_K  + (size_t)b * SS * 8;
    const uint4* Vhg = (const uint4*)g_Vh + (size_t)b * DD * 512;
    const uint4* Vlg = (const uint4*)g_Vl + (size_t)b * DD * 512;

    stage_tile(pbase,         ptid, split * NSPLIT + 0, Kg, Vhg, Vlg); CP_COMMIT();
    stage_tile(pbase + 12288, ptid, split * NSPLIT + 1, Kg, Vhg, Vlg); CP_COMMIT();

    uint32_t w0 = M0[0], w1 = M1[0];           // mask word pipeline

    for (int j = 0; j < NSPLIT; j++) {
        const char* cur = psm + (j & 1) * 12288;

        // prefetch next tile's mask words (L2-resident, hidden under MMAs)
        uint32_t wn0 = 0, wn1 = 0;
        if (j + 1 < NSPLIT) { wn0 = __ldg(&M0[j + 1]); wn1 = __ldg(&M1[j + 1]); }

        CP_WAIT1();
        BARP(1 + split);

        // ---- S = (Qh + Ql) * K_rn (2-term) ----
        float4 S[4];
        #pragma unroll
        for (int n = 0; n < 4; n++) S[n] = make_float4(0.f, 0.f, 0.f, 0.f);
        #pragma unroll
        for (int kc = 0; kc < 4; kc++) {
            #pragma unroll
            for (int n = 0; n < 4; n++) {
                uint32_t cb = (lq + kc * 8) * 4;
                const char* base = cur + (n * 8 + gr) * 128 + (cb & 15);
                uint32_t b0 = *(const uint32_t*)(base + (((cb >> 4) ^ gr) << 4));
                uint32_t b1 = *(const uint32_t*)(base + ((((cb >> 4) + 1) ^ gr) << 4));
                mma16816(S[n], Ah[kc], b0, b1);
                mma16816(S[n], Al[kc], b0, b1);
            }
        }

        // ---- mask + exp ----
        #pragma unroll
        for (int n = 0; n < 4; n++) {
            int sh = n * 8 + lq * 2;
            S[n].x = ((w0 >> sh) & 1u)       ? 0.f : __expf(S[n].x * 0.125f);
            S[n].y = ((w0 >> (sh + 1)) & 1u) ? 0.f : __expf(S[n].y * 0.125f);
            S[n].z = ((w1 >> sh) & 1u)       ? 0.f : __expf(S[n].z * 0.125f);
            S[n].w = ((w1 >> (sh + 1)) & 1u) ? 0.f : __expf(S[n].w * 0.125f);
            l0 += S[n].x + S[n].y;
            l1 += S[n].z + S[n].w;
        }
        w0 = wn0; w1 = wn1;

        // ---- O += P V (3-term hi/lo) ----
        #pragma unroll
        for (int kc = 0; kc < 2; kc++) {
            float4 pa = S[2 * kc], pb = S[2 * kc + 1];
            uint32_t Ph[4] = {hip(pa.x, pa.y), hip(pa.z, pa.w),
                              hip(pb.x, pb.y), hip(pb.z, pb.w)};
            uint32_t Pl[4] = {lop(pa.x, pa.y), lop(pa.z, pa.w),
                              lop(pb.x, pb.y), lop(pb.z, pb.w)};
            #pragma unroll
            for (int n = 0; n < 8; n++) {
                uint32_t cb = (lq + kc * 8) * 4;
                const char* base = cur + 4096 + (n * 8 + gr) * 64 + (cb & 15);
                const char* a0 = base + (((cb >> 4) ^ (gr >> 1)) << 4);
                const char* a1 = base + ((((cb >> 4) + 1) ^ (gr >> 1)) << 4);
                uint32_t vh0 = *(const uint32_t*)a0;
                uint32_t vh1 = *(const uint32_t*)a1;
                uint32_t vl0 = *(const uint32_t*)(a0 + 4096);
                uint32_t vl1 = *(const uint32_t*)(a1 + 4096);
                mma16816(O[n], Ph, vh0, vh1);
                mma16816(O[n], Pl, vh0, vh1);
                mma16816(O[n], Ph, vl0, vl1);
            }
        }

        BARP(1 + split);
        if (j + 2 < NSPLIT)
            stage_tile(pbase + (j & 1) * 12288, ptid, split * NSPLIT + j + 2,
                       Kg, Vhg, Vlg);
        CP_COMMIT();
    }

    // ---- quad-reduce row sums ----
    l0 += __shfl_xor_sync(0xFFFFFFFFu, l0, 1);
    l0 += __shfl_xor_sync(0xFFFFFFFFu, l0, 2);
    l1 += __shfl_xor_sync(0xFFFFFFFFu, l1, 1);
    l1 += __shfl_xor_sync(0xFFFFFFFFu, l1, 2);

    // ---- combine the two k-splits via smem ----
    __syncthreads();                     // all buffers dead now
    float* cO = (float*)sm;              // 32 x 64 f32 = 8KB
    float* cL = (float*)(sm + 8192);     // 32 f32
    if (split == 1) {
        #pragma unroll
        for (int n = 0; n < 8; n++) {
            int c = n * 8 + lq * 2;
            cO[qloc * 64 + c]           = O[n].x;
            cO[qloc * 64 + c + 1]       = O[n].y;
            cO[(qloc + 8) * 64 + c]     = O[n].z;
            cO[(qloc + 8) * 64 + c + 1] = O[n].w;
        }
        if (lq == 0) { cL[qloc] = l0; cL[qloc + 8] = l1; }
    }
    __syncthreads();
    if (split == 0) {
        const float inv0 = 1.0f / (l0 + cL[qloc]);
        const float inv1 = 1.0f / (l1 + cL[qloc + 8]);
        float* o0 = out + (size_t)(b * SS + qr) * DD;
        float* o1 = o0 + (size_t)8 * DD;
        #pragma unroll
        for (int n = 0; n < 8; n++) {
            int c = n * 8 + lq * 2;
            *(float2*)&o0[c] = make_float2((O[n].x + cO[qloc * 64 + c]) * inv0,
                                           (O[n].y + cO[qloc * 64 + c + 1]) * inv0);
            *(float2*)&o1[c] = make_float2((O[n].z + cO[(qloc + 8) * 64 + c]) * inv1,
                                           (O[n].w + cO[(qloc + 8) * 64 + c + 1]) * inv1);
        }
    }
}

// ---------------------------------------------------------------------------
extern "C" void kernel_launch(void* const* d_in, const int* in_sizes, int n_in,
                              void* d_out, int out_size)
{
    const float* queries = (const float*)d_in[0];
    const float* keys    = (const float*)d_in[1];
    const float* values  = (const float*)d_in[2];
    const int*   mask    = (const int*)d_in[3];
    const float* W_q = (const float*)d_in[4];
    const float* W_k = (const float*)d_in[5];
    const float* W_v = (const float*)d_in[6];

    prep_kernel<<<896, 256>>>(queries, keys, values, W_q, W_k, W_v, mask);
    attn_kernel<<<dim3(SS / 32, BB), 128>>>((float*)d_out);
}

// round 12
// speedup vs baseline: 1.1487x; 1.1487x over previous
#include <cuda_runtime.h>
#include <cstdint>

#define BB 4
#define SS 4096
#define EE 1024
#define DD 64
#define TK 32
#define NT (SS / TK)      // 128 key tiles total
#define NSPLIT 64         // tiles per k-split

// ---------------- device scratch ----------------
__device__ uint32_t g_Q [BB * SS * DD / 2];   // [s][d] rounded bf16 pairs
__device__ uint32_t g_K [BB * SS * DD / 2];   // [s][d] rounded bf16 pairs
__device__ uint32_t g_Vh[BB * DD * SS / 2];   // [d][s] hi (V^T)
__device__ uint32_t g_Vl[BB * DD * SS / 2];   // [d][s] lo
__device__ uint32_t g_Mb[BB * SS * (SS / 32)];  // bit-packed mask, 8MB

// ---------------- helpers ----------------
__device__ __forceinline__ uint32_t hip(float a, float b) {
    return __byte_perm(__float_as_uint(a), __float_as_uint(b), 0x7632);
}
__device__ __forceinline__ float lof(float a) {
    return a - __uint_as_float(__float_as_uint(a) & 0xFFFF0000u);
}
__device__ __forceinline__ uint32_t lop(float a, float b) {
    uint32_t r;
    asm("cvt.rn.bf16x2.f32 %0, %1, %2;" : "=r"(r) : "f"(lof(b)), "f"(lof(a)));
    return r;
}
__device__ __forceinline__ uint32_t rnp(float a, float b) {   // rounded pair
    uint32_t r;
    asm("cvt.rn.bf16x2.f32 %0, %1, %2;" : "=r"(r) : "f"(b), "f"(a));
    return r;
}
__device__ __forceinline__ unsigned short f2bf(float f) {
    unsigned short u; asm("cvt.rn.bf16.f32 %0, %1;" : "=h"(u) : "f"(f)); return u;
}
__device__ __forceinline__ float ex2a(float x) {              // 2^x approx
    float r; asm("ex2.approx.f32 %0, %1;" : "=f"(r) : "f"(x)); return r;
}
#define SCL 0.18033688011112042f   /* 0.125 * log2(e) */
__device__ __forceinline__ void mma16816(float4& c, const uint32_t a[4],
                                         uint32_t b0, uint32_t b1) {
    asm volatile(
        "mma.sync.aligned.m16n8k16.row.col.f32.bf16.bf16.f32 "
        "{%0,%1,%2,%3}, {%4,%5,%6,%7}, {%8,%9}, {%0,%1,%2,%3};"
        : "+f"(c.x), "+f"(c.y), "+f"(c.z), "+f"(c.w)
        : "r"(a[0]), "r"(a[1]), "r"(a[2]), "r"(a[3]), "r"(b0), "r"(b1));
}
__device__ __forceinline__ uint32_t smem_u32(const void* p) {
    uint32_t a;
    asm("{ .reg .u64 t; cvta.to.shared.u64 t, %1; cvt.u32.u64 %0, t; }" : "=r"(a) : "l"(p));
    return a;
}
__device__ __forceinline__ void cpa(uint32_t dst, const void* src) {
    asm volatile("cp.async.cg.shared.global [%0], [%1], 16;" :: "r"(dst), "l"(src));
}
#define CP_COMMIT() asm volatile("cp.async.commit_group;" ::: "memory")
#define CP_WAIT1()  asm volatile("cp.async.wait_group 1;" ::: "memory")
#define BARP(id)    asm volatile("bar.sync %0, 64;" :: "r"(id) : "memory")

#define RSTRIDE 144   // proj smem row stride

// ---------------------------------------------------------------------------
// Fused prep kernel: 896 CTAs = 128 groups of 7, INTERLEAVED:
//   bx%7 < 3  -> projection CTA  (pidx = (bx/7)*3 + bx%7, 0..383)
//   bx%7 >= 3 -> mask-pack CTA   (qidx = (bx/7)*4 + bx%7-3, 0..511)
// DRAM-bound pack CTAs co-resident with tensor-bound proj CTAs from wave 1.
// ---------------------------------------------------------------------------
__global__ __launch_bounds__(256) void prep_kernel(
    const float* __restrict__ Xq, const float* __restrict__ Xk,
    const float* __restrict__ Xv,
    const float* __restrict__ Wq, const float* __restrict__ Wk,
    const float* __restrict__ Wv, const int* __restrict__ mask)
{
    const int tid = threadIdx.x;
    const int w = tid >> 5, l = tid & 31;
    const int grp = blockIdx.x / 7, lane7 = blockIdx.x % 7;

    if (lane7 >= 3) {
        // ---- mask bit-pack: 2M words over 512 CTAs x 8 warps ----
        const int gw = (grp * 4 + lane7 - 3) * 8 + w;   // 0..4095
        #pragma unroll 4
        for (int it = 0; it < 16; it++) {
            size_t wbase = (size_t)gw * 512 + it * 32;
            size_t ibase = wbase * 32;
            int v[32];
            #pragma unroll
            for (int j = 0; j < 32; j++) v[j] = mask[ibase + j * 32 + l];
            uint32_t myw = 0;
            #pragma unroll
            for (int j = 0; j < 32; j++) {
                uint32_t bt = __ballot_sync(0xFFFFFFFFu, v[j] != 0);
                if (l == j) myw = bt;
            }
            g_Mb[wbase + l] = myw;
        }
        return;
    }

    const int pidx = grp * 3 + lane7;       // 0..383
    const int px = pidx & 127;
    const int py = pidx >> 7;               // 0=Q, 1=K, 2=V

    const float* __restrict__ X;
    const float* __restrict__ W;
    if (py == 0)      { X = Xq; W = Wq; }
    else if (py == 1) { X = Xk; W = Wk; }
    else              { X = Xv; W = Wv; }

    __shared__ __align__(16) char sWh[64 * RSTRIDE];
    __shared__ __align__(16) char sWl[64 * RSTRIDE];

    const int gr = l >> 2, lq = l & 3;
    const int r0 = px * 128;

    float4 C[8];
    #pragma unroll
    for (int n = 0; n < 8; n++) C[n] = make_float4(0.f, 0.f, 0.f, 0.f);

    for (int e0 = 0; e0 < EE; e0 += 64) {
        __syncthreads();
        #pragma unroll
        for (int i = 0; i < 4; i++) {
            int idx = tid + i * 256;
            int d = idx >> 4, c4 = idx & 15;
            float4 wv = *(const float4*)&W[(size_t)d * EE + e0 + c4 * 4];
            *(uint2*)(sWh + d * RSTRIDE + c4 * 8) = make_uint2(hip(wv.x, wv.y), hip(wv.z, wv.w));
            *(uint2*)(sWl + d * RSTRIDE + c4 * 8) = make_uint2(lop(wv.x, wv.y), lop(wv.z, wv.w));
        }
        __syncthreads();

        const float* Xw = X + (size_t)(r0 + w * 16) * EE + e0;
        #pragma unroll
        for (int kc = 0; kc < 4; kc++) {
            float2 x00 = *(const float2*)&Xw[gr * EE + lq * 2 + kc * 16];
            float2 x10 = *(const float2*)&Xw[(gr + 8) * EE + lq * 2 + kc * 16];
            float2 x01 = *(const float2*)&Xw[gr * EE + lq * 2 + kc * 16 + 8];
            float2 x11 = *(const float2*)&Xw[(gr + 8) * EE + lq * 2 + kc * 16 + 8];
            uint32_t Ah[4] = {hip(x00.x, x00.y), hip(x10.x, x10.y),
                              hip(x01.x, x01.y), hip(x11.x, x11.y)};
            uint32_t Al[4] = {lop(x00.x, x00.y), lop(x10.x, x10.y),
                              lop(x01.x, x01.y), lop(x11.x, x11.y)};
            #pragma unroll
            for (int n = 0; n < 8; n++) {
                const char* bh = sWh + (n * 8 + gr) * RSTRIDE + (lq + kc * 8) * 4;
                const char* bl = sWl + (n * 8 + gr) * RSTRIDE + (lq + kc * 8) * 4;
                uint32_t bh0 = *(const uint32_t*)bh;
                uint32_t bh1 = *(const uint32_t*)(bh + 16);
                uint32_t bl0 = *(const uint32_t*)bl;
                uint32_t bl1 = *(const uint32_t*)(bl + 16);
                mma16816(C[n], Ah, bh0, bh1);
                mma16816(C[n], Al, bh0, bh1);
                mma16816(C[n], Ah, bl0, bl1);
            }
        }
    }

    const int r = r0 + w * 16 + gr;
    if (py < 2) {
        uint32_t* T = (py == 0) ? g_Q : g_K;
        #pragma unroll
        for (int n = 0; n < 8; n++) {
            int d2 = n * 4 + lq;
            T[(size_t)r * 32 + d2]       = rnp(C[n].x, C[n].y);
            T[(size_t)(r + 8) * 32 + d2] = rnp(C[n].z, C[n].w);
        }
    } else {
        unsigned short* Vh16 = (unsigned short*)g_Vh;
        unsigned short* Vl16 = (unsigned short*)g_Vl;
        const int bi = r >> 12, s = r & 4095;
        #pragma unroll
        for (int n = 0; n < 8; n++) {
            int d = n * 8 + lq * 2;
            size_t o0 = (size_t)(bi * DD + d) * SS + s;
            size_t o1 = (size_t)(bi * DD + d + 1) * SS + s;
            Vh16[o0]     = (unsigned short)(__float_as_uint(C[n].x) >> 16);
            Vl16[o0]     = f2bf(lof(C[n].x));
            Vh16[o1]     = (unsigned short)(__float_as_uint(C[n].y) >> 16);
            Vl16[o1]     = f2bf(lof(C[n].y));
            Vh16[o0 + 8] = (unsigned short)(__float_as_uint(C[n].z) >> 16);
            Vl16[o0 + 8] = f2bf(lof(C[n].z));
            Vh16[o1 + 8] = (unsigned short)(__float_as_uint(C[n].w) >> 16);
            Vl16[o1 + 8] = f2bf(lof(C[n].w));
        }
    }
}

// ---------------------------------------------------------------------------
// Attention, split-K=2 in-CTA: 128 thr / 4 warps / 32 q rows.
// S = Q_rn * K_rn (1-term); O += P V (3-term hi/lo).
// Warp-pair p owns k-tiles [p*64, p*64+64), own double buffer + named barrier.
// Buffer: K 4KB | Vh 4KB | Vl 4KB; 4 CTAs/SM -> 512 CTAs one wave.
// ---------------------------------------------------------------------------
__device__ __forceinline__ void stage_tile(
    uint32_t base, int ptid, int t,
    const uint4* Kg, const uint4* Vhg, const uint4* Vlg)
{
    const int k0 = t * TK;
    #pragma unroll
    for (int j = 0; j < 4; j++) {       // K: 32 rows x 8 chunks (4KB)
        int idx = ptid + j * 64;
        int r = idx >> 3, c = idx & 7;
        uint32_t d = base + r * 128 + ((c ^ (r & 7)) << 4);
        cpa(d, Kg + (size_t)(k0 + r) * 8 + c);
    }
    #pragma unroll
    for (int j = 0; j < 4; j++) {       // V^T: 64 rows x 4 chunks (4KB each)
        int idx = ptid + j * 64;
        int r = idx >> 2, c = idx & 3;
        uint32_t d = base + 4096 + r * 64 + ((c ^ ((r >> 1) & 3)) << 4);
        cpa(d,        Vhg + (size_t)r * 512 + (k0 >> 3) + c);
        cpa(d + 4096, Vlg + (size_t)r * 512 + (k0 >> 3) + c);
    }
}

__global__ __launch_bounds__(128, 4) void attn_kernel(float* __restrict__ out)
{
    __shared__ __align__(16) char sm[49152];

    const int tid = threadIdx.x;
    const int w = tid >> 5, l = tid & 31;
    const int gr = l >> 2, lq = l & 3;
    const int split = w >> 1, sub = w & 1;
    const int ptid = tid & 63;
    const int b = blockIdx.y;
    const int qloc = sub * 16 + gr;
    const int qr = blockIdx.x * 32 + qloc;

    const uint32_t pbase = smem_u32(sm) + split * 24576;
    const char* psm = sm + split * 24576;

    // Q fragments (rounded bf16, 1-term)
    uint32_t Ah[4][4];
    {
        const uint32_t* Qp = g_Q + (size_t)b * SS * 32;
        #pragma unroll
        for (int kc = 0; kc < 4; kc++) {
            int c0 = lq + kc * 8;
            Ah[kc][0] = Qp[(size_t)qr * 32 + c0];
            Ah[kc][1] = Qp[(size_t)(qr + 8) * 32 + c0];
            Ah[kc][2] = Qp[(size_t)qr * 32 + c0 + 4];
            Ah[kc][3] = Qp[(size_t)(qr + 8) * 32 + c0 + 4];
        }
    }

    float4 O[8];
    #pragma unroll
    for (int n = 0; n < 8; n++) O[n] = make_float4(0.f, 0.f, 0.f, 0.f);
    float l0 = 0.f, l1 = 0.f;

    const uint32_t* M0 = g_Mb + (size_t)(b * SS + qr) * NT + split * NSPLIT;
    const uint32_t* M1 = M0 + (size_t)8 * NT;
    const uint4* Kg  = (const uint4*)g_K  + (size_t)b * SS * 8;
    const uint4* Vhg = (const uint4*)g_Vh + (size_t)b * DD * 512;
    const uint4* Vlg = (const uint4*)g_Vl + (size_t)b * DD * 512;

    stage_tile(pbase,         ptid, split * NSPLIT + 0, Kg, Vhg, Vlg); CP_COMMIT();
    stage_tile(pbase + 12288, ptid, split * NSPLIT + 1, Kg, Vhg, Vlg); CP_COMMIT();

    uint32_t w0 = M0[0], w1 = M1[0];           // mask word pipeline

    for (int j = 0; j < NSPLIT; j++) {
        const char* cur = psm + (j & 1) * 12288;

        uint32_t wn0 = 0, wn1 = 0;
        if (j + 1 < NSPLIT) { wn0 = __ldg(&M0[j + 1]); wn1 = __ldg(&M1[j + 1]); }

        CP_WAIT1();
        BARP(1 + split);

        // ---- S = Q_rn * K_rn (1-term) ----
        float4 S[4];
        #pragma unroll
        for (int n = 0; n < 4; n++) S[n] = make_float4(0.f, 0.f, 0.f, 0.f);
        #pragma unroll
        for (int kc = 0; kc < 4; kc++) {
            #pragma unroll
            for (int n = 0; n < 4; n++) {
                uint32_t cb = (lq + kc * 8) * 4;
                const char* base = cur + (n * 8 + gr) * 128 + (cb & 15);
                uint32_t b0 = *(const uint32_t*)(base + (((cb >> 4) ^ gr) << 4));
                uint32_t b1 = *(const uint32_t*)(base + ((((cb >> 4) + 1) ^ gr) << 4));
                mma16816(S[n], Ah[kc], b0, b1);
            }
        }

        // ---- mask + exp (ex2.approx, folded 0.125*log2e) ----
        #pragma unroll
        for (int n = 0; n < 4; n++) {
            int sh = n * 8 + lq * 2;
            S[n].x = ((w0 >> sh) & 1u)       ? 0.f : ex2a(S[n].x * SCL);
            S[n].y = ((w0 >> (sh + 1)) & 1u) ? 0.f : ex2a(S[n].y * SCL);
            S[n].z = ((w1 >> sh) & 1u)       ? 0.f : ex2a(S[n].z * SCL);
            S[n].w = ((w1 >> (sh + 1)) & 1u) ? 0.f : ex2a(S[n].w * SCL);
            l0 += S[n].x + S[n].y;
            l1 += S[n].z + S[n].w;
        }
        w0 = wn0; w1 = wn1;

        // ---- O += P V (3-term hi/lo) ----
        #pragma unroll
        for (int kc = 0; kc < 2; kc++) {
            float4 pa = S[2 * kc], pb = S[2 * kc + 1];
            uint32_t Ph[4] = {hip(pa.x, pa.y), hip(pa.z, pa.w),
                              hip(pb.x, pb.y), hip(pb.z, pb.w)};
            uint32_t Pl[4] = {lop(pa.x, pa.y), lop(pa.z, pa.w),
                              lop(pb.x, pb.y), lop(pb.z, pb.w)};
            #pragma unroll
            for (int n = 0; n < 8; n++) {
                uint32_t cb = (lq + kc * 8) * 4;
                const char* base = cur + 4096 + (n * 8 + gr) * 64 + (cb & 15);
                const char* a0 = base + (((cb >> 4) ^ (gr >> 1)) << 4);
                const char* a1 = base + ((((cb >> 4) + 1) ^ (gr >> 1)) << 4);
                uint32_t vh0 = *(const uint32_t*)a0;
                uint32_t vh1 = *(const uint32_t*)a1;
                uint32_t vl0 = *(const uint32_t*)(a0 + 4096);
                uint32_t vl1 = *(const uint32_t*)(a1 + 4096);
                mma16816(O[n], Ph, vh0, vh1);
                mma16816(O[n], Pl, vh0, vh1);
                mma16816(O[n], Ph, vl0, vl1);
            }
        }

        BARP(1 + split);
        if (j + 2 < NSPLIT)
            stage_tile(pbase + (j & 1) * 12288, ptid, split * NSPLIT + j + 2,
                       Kg, Vhg, Vlg);
        CP_COMMIT();
    }

    // ---- quad-reduce row sums ----
    l0 += __shfl_xor_sync(0xFFFFFFFFu, l0, 1);
    l0 += __shfl_xor_sync(0xFFFFFFFFu, l0, 2);
    l1 += __shfl_xor_sync(0xFFFFFFFFu, l1, 1);
    l1 += __shfl_xor_sync(0xFFFFFFFFu, l1, 2);

    // ---- combine the two k-splits via smem ----
    __syncthreads();                     // all buffers dead now
    float* cO = (float*)sm;              // 32 x 64 f32 = 8KB
    float* cL = (float*)(sm + 8192);     // 32 f32
    if (split == 1) {
        #pragma unroll
        for (int n = 0; n < 8; n++) {
            int c = n * 8 + lq * 2;
            cO[qloc * 64 + c]           = O[n].x;
            cO[qloc * 64 + c + 1]       = O[n].y;
            cO[(qloc + 8) * 64 + c]     = O[n].z;
            cO[(qloc + 8) * 64 + c + 1] = O[n].w;
        }
        if (lq == 0) { cL[qloc] = l0; cL[qloc + 8] = l1; }
    }
    __syncthreads();
    if (split == 0) {
        const float inv0 = 1.0f / (l0 + cL[qloc]);
        const float inv1 = 1.0f / (l1 + cL[qloc + 8]);
        float* o0 = out + (size_t)(b * SS + qr) * DD;
        float* o1 = o0 + (size_t)8 * DD;
        #pragma unroll
        for (int n = 0; n < 8; n++) {
            int c = n * 8 + lq * 2;
            *(float2*)&o0[c] = make_float2((O[n].x + cO[qloc * 64 + c]) * inv0,
                                           (O[n].y + cO[qloc * 64 + c + 1]) * inv0);
            *(float2*)&o1[c] = make_float2((O[n].z + cO[(qloc + 8) * 64 + c]) * inv1,
                                           (O[n].w + cO[(qloc + 8) * 64 + c + 1]) * inv1);
        }
    }
}

// ---------------------------------------------------------------------------
extern "C" void kernel_launch(void* const* d_in, const int* in_sizes, int n_in,
                              void* d_out, int out_size)
{
    const float* queries = (const float*)d_in[0];
    const float* keys    = (const float*)d_in[1];
    const float* values  = (const float*)d_in[2];
    const int*   mask    = (const int*)d_in[3];
    const float* W_q = (const float*)d_in[4];
    const float* W_k = (const float*)d_in[5];
    const float* W_v = (const float*)d_in[6];

    prep_kernel<<<896, 256>>>(queries, keys, values, W_q, W_k, W_v, mask);
    attn_kernel<<<dim3(SS / 32, BB), 128>>>((float*)d_out);
}

// round 13
// speedup vs baseline: 1.5353x; 1.3365x over previous
#include <cuda_runtime.h>
#include <cstdint>

#define BB 4
#define SS 4096
#define EE 1024
#define DD 64
#define TK 32
#define NT (SS / TK)      // 128 key tiles total
#define NSPLIT 64         // tiles per k-split

// ---------------- device scratch ----------------
__device__ uint32_t g_Q [BB * SS * DD / 2];   // [s][d] rounded bf16 pairs
__device__ uint32_t g_K [BB * SS * DD / 2];   // [s][d] rounded bf16 pairs
__device__ uint32_t g_V [BB * DD * SS / 2];   // [d][s] fp16 pairs (V^T)
__device__ uint32_t g_Mb[BB * SS * (SS / 32)];  // bit-packed mask, 8MB

// ---------------- helpers ----------------
__device__ __forceinline__ uint32_t hip(float a, float b) {
    return __byte_perm(__float_as_uint(a), __float_as_uint(b), 0x7632);
}
__device__ __forceinline__ float lof(float a) {
    return a - __uint_as_float(__float_as_uint(a) & 0xFFFF0000u);
}
__device__ __forceinline__ uint32_t lop(float a, float b) {
    uint32_t r;
    asm("cvt.rn.bf16x2.f32 %0, %1, %2;" : "=r"(r) : "f"(lof(b)), "f"(lof(a)));
    return r;
}
__device__ __forceinline__ uint32_t rnp(float a, float b) {   // bf16 pair, lo=a hi=b
    uint32_t r;
    asm("cvt.rn.bf16x2.f32 %0, %1, %2;" : "=r"(r) : "f"(b), "f"(a));
    return r;
}
__device__ __forceinline__ uint32_t rnh(float a, float b) {   // fp16 pair, lo=a hi=b
    uint32_t r;
    asm("cvt.rn.f16x2.f32 %0, %1, %2;" : "=r"(r) : "f"(b), "f"(a));
    return r;
}
__device__ __forceinline__ unsigned short f2h(float f) {
    unsigned short u; asm("cvt.rn.f16.f32 %0, %1;" : "=h"(u) : "f"(f)); return u;
}
__device__ __forceinline__ float ex2a(float x) {              // 2^x approx
    float r; asm("ex2.approx.f32 %0, %1;" : "=f"(r) : "f"(x)); return r;
}
#define SCL 0.18033688011112042f   /* 0.125 * log2(e) */
__device__ __forceinline__ void mma16816(float4& c, const uint32_t a[4],
                                         uint32_t b0, uint32_t b1) {
    asm volatile(
        "mma.sync.aligned.m16n8k16.row.col.f32.bf16.bf16.f32 "
        "{%0,%1,%2,%3}, {%4,%5,%6,%7}, {%8,%9}, {%0,%1,%2,%3};"
        : "+f"(c.x), "+f"(c.y), "+f"(c.z), "+f"(c.w)
        : "r"(a[0]), "r"(a[1]), "r"(a[2]), "r"(a[3]), "r"(b0), "r"(b1));
}
__device__ __forceinline__ void mma16816h(float4& c, const uint32_t a[4],
                                          uint32_t b0, uint32_t b1) {
    asm volatile(
        "mma.sync.aligned.m16n8k16.row.col.f32.f16.f16.f32 "
        "{%0,%1,%2,%3}, {%4,%5,%6,%7}, {%8,%9}, {%0,%1,%2,%3};"
        : "+f"(c.x), "+f"(c.y), "+f"(c.z), "+f"(c.w)
        : "r"(a[0]), "r"(a[1]), "r"(a[2]), "r"(a[3]), "r"(b0), "r"(b1));
}
__device__ __forceinline__ uint32_t smem_u32(const void* p) {
    uint32_t a;
    asm("{ .reg .u64 t; cvta.to.shared.u64 t, %1; cvt.u32.u64 %0, t; }" : "=r"(a) : "l"(p));
    return a;
}
__device__ __forceinline__ void cpa(uint32_t dst, const void* src) {
    asm volatile("cp.async.cg.shared.global [%0], [%1], 16;" :: "r"(dst), "l"(src));
}
#define CP_COMMIT() asm volatile("cp.async.commit_group;" ::: "memory")
#define CP_WAIT1()  asm volatile("cp.async.wait_group 1;" ::: "memory")
#define BARP(id)    asm volatile("bar.sync %0, 64;" :: "r"(id) : "memory")

#define RSTRIDE 144   // proj smem row stride

// ---------------------------------------------------------------------------
// Fused prep kernel (896 CTAs x 256 thr), PROJ CTAs FIRST (measured best):
//   bx in [0,384)   : projection. py = bx/128: 0=Q rn, 1=K rn, 2=V^T fp16
//   bx in [384,896) : mask bit-pack over 512 CTAs.
// ---------------------------------------------------------------------------
__global__ __launch_bounds__(256) void prep_kernel(
    const float* __restrict__ Xq, const float* __restrict__ Xk,
    const float* __restrict__ Xv,
    const float* __restrict__ Wq, const float* __restrict__ Wk,
    const float* __restrict__ Wv, const int* __restrict__ mask)
{
    const int tid = threadIdx.x;
    const int w = tid >> 5, l = tid & 31;

    if (blockIdx.x >= 384) {
        // ---- mask bit-pack: 2M words over 512 CTAs x 8 warps ----
        const int gw = (blockIdx.x - 384) * 8 + w;     // 0..4095
        #pragma unroll 4
        for (int it = 0; it < 16; it++) {
            size_t wbase = (size_t)gw * 512 + it * 32;
            size_t ibase = wbase * 32;
            int v[32];
            #pragma unroll
            for (int j = 0; j < 32; j++) v[j] = mask[ibase + j * 32 + l];
            uint32_t myw = 0;
            #pragma unroll
            for (int j = 0; j < 32; j++) {
                uint32_t bt = __ballot_sync(0xFFFFFFFFu, v[j] != 0);
                if (l == j) myw = bt;
            }
            g_Mb[wbase + l] = myw;
        }
        return;
    }

    const int px = blockIdx.x & 127;
    const int py = blockIdx.x >> 7;      // 0=Q, 1=K, 2=V

    const float* __restrict__ X;
    const float* __restrict__ W;
    if (py == 0)      { X = Xq; W = Wq; }
    else if (py == 1) { X = Xk; W = Wk; }
    else              { X = Xv; W = Wv; }

    __shared__ __align__(16) char sWh[64 * RSTRIDE];
    __shared__ __align__(16) char sWl[64 * RSTRIDE];

    const int gr = l >> 2, lq = l & 3;
    const int r0 = px * 128;

    float4 C[8];
    #pragma unroll
    for (int n = 0; n < 8; n++) C[n] = make_float4(0.f, 0.f, 0.f, 0.f);

    for (int e0 = 0; e0 < EE; e0 += 64) {
        __syncthreads();
        #pragma unroll
        for (int i = 0; i < 4; i++) {
            int idx = tid + i * 256;
            int d = idx >> 4, c4 = idx & 15;
            float4 wv = *(const float4*)&W[(size_t)d * EE + e0 + c4 * 4];
            *(uint2*)(sWh + d * RSTRIDE + c4 * 8) = make_uint2(hip(wv.x, wv.y), hip(wv.z, wv.w));
            *(uint2*)(sWl + d * RSTRIDE + c4 * 8) = make_uint2(lop(wv.x, wv.y), lop(wv.z, wv.w));
        }
        __syncthreads();

        const float* Xw = X + (size_t)(r0 + w * 16) * EE + e0;
        #pragma unroll
        for (int kc = 0; kc < 4; kc++) {
            float2 x00 = *(const float2*)&Xw[gr * EE + lq * 2 + kc * 16];
            float2 x10 = *(const float2*)&Xw[(gr + 8) * EE + lq * 2 + kc * 16];
            float2 x01 = *(const float2*)&Xw[gr * EE + lq * 2 + kc * 16 + 8];
            float2 x11 = *(const float2*)&Xw[(gr + 8) * EE + lq * 2 + kc * 16 + 8];
            uint32_t Ah[4] = {hip(x00.x, x00.y), hip(x10.x, x10.y),
                              hip(x01.x, x01.y), hip(x11.x, x11.y)};
            uint32_t Al[4] = {lop(x00.x, x00.y), lop(x10.x, x10.y),
                              lop(x01.x, x01.y), lop(x11.x, x11.y)};
            #pragma unroll
            for (int n = 0; n < 8; n++) {
                const char* bh = sWh + (n * 8 + gr) * RSTRIDE + (lq + kc * 8) * 4;
                const char* bl = sWl + (n * 8 + gr) * RSTRIDE + (lq + kc * 8) * 4;
                uint32_t bh0 = *(const uint32_t*)bh;
                uint32_t bh1 = *(const uint32_t*)(bh + 16);
                uint32_t bl0 = *(const uint32_t*)bl;
                uint32_t bl1 = *(const uint32_t*)(bl + 16);
                mma16816(C[n], Ah, bh0, bh1);
                mma16816(C[n], Al, bh0, bh1);
                mma16816(C[n], Ah, bl0, bl1);
            }
        }
    }

    const int r = r0 + w * 16 + gr;
    if (py < 2) {
        uint32_t* T = (py == 0) ? g_Q : g_K;
        #pragma unroll
        for (int n = 0; n < 8; n++) {
            int d2 = n * 4 + lq;
            T[(size_t)r * 32 + d2]       = rnp(C[n].x, C[n].y);
            T[(size_t)(r + 8) * 32 + d2] = rnp(C[n].z, C[n].w);
        }
    } else {
        unsigned short* V16 = (unsigned short*)g_V;
        const int bi = r >> 12, s = r & 4095;
        #pragma unroll
        for (int n = 0; n < 8; n++) {
            int d = n * 8 + lq * 2;
            size_t o0 = (size_t)(bi * DD + d) * SS + s;
            size_t o1 = (size_t)(bi * DD + d + 1) * SS + s;
            V16[o0]     = f2h(C[n].x);
            V16[o1]     = f2h(C[n].y);
            V16[o0 + 8] = f2h(C[n].z);
            V16[o1 + 8] = f2h(C[n].w);
        }
    }
}

// ---------------------------------------------------------------------------
// Attention, split-K=2 in-CTA: 128 thr / 4 warps / 32 q rows.
// S = Q_rn * K_rn (bf16, 1 term); O += P_f16 * V_f16 (1 term).
// Buffer: K 4KB | V 4KB = 8KB/tile, double buffered per split -> 32KB smem.
// 4 CTAs/SM -> all 512 CTAs in one wave.
// ---------------------------------------------------------------------------
__device__ __forceinline__ void stage_tile(
    uint32_t base, int ptid, int t, const uint4* Kg, const uint4* Vg)
{
    const int k0 = t * TK;
    #pragma unroll
    for (int j = 0; j < 4; j++) {       // K: 32 rows x 8 chunks (4KB)
        int idx = ptid + j * 64;
        int r = idx >> 3, c = idx & 7;
        uint32_t d = base + r * 128 + ((c ^ (r & 7)) << 4);
        cpa(d, Kg + (size_t)(k0 + r) * 8 + c);
    }
    #pragma unroll
    for (int j = 0; j < 4; j++) {       // V^T: 64 rows x 4 chunks (4KB)
        int idx = ptid + j * 64;
        int r = idx >> 2, c = idx & 3;
        uint32_t d = base + 4096 + r * 64 + ((c ^ ((r >> 1) & 3)) << 4);
        cpa(d, Vg + (size_t)r * 512 + (k0 >> 3) + c);
    }
}

__global__ __launch_bounds__(128, 4) void attn_kernel(float* __restrict__ out)
{
    __shared__ __align__(16) char sm[32768];

    const int tid = threadIdx.x;
    const int w = tid >> 5, l = tid & 31;
    const int gr = l >> 2, lq = l & 3;
    const int split = w >> 1, sub = w & 1;
    const int ptid = tid & 63;
    const int b = blockIdx.y;
    const int qloc = sub * 16 + gr;
    const int qr = blockIdx.x * 32 + qloc;

    const uint32_t pbase = smem_u32(sm) + split * 16384;
    const char* psm = sm + split * 16384;

    // Q fragments (rounded bf16)
    uint32_t Ah[4][4];
    {
        const uint32_t* Qp = g_Q + (size_t)b * SS * 32;
        #pragma unroll
        for (int kc = 0; kc < 4; kc++) {
            int c0 = lq + kc * 8;
            Ah[kc][0] = Qp[(size_t)qr * 32 + c0];
            Ah[kc][1] = Qp[(size_t)(qr + 8) * 32 + c0];
            Ah[kc][2] = Qp[(size_t)qr * 32 + c0 + 4];
            Ah[kc][3] = Qp[(size_t)(qr + 8) * 32 + c0 + 4];
        }
    }

    float4 O[8];
    #pragma unroll
    for (int n = 0; n < 8; n++) O[n] = make_float4(0.f, 0.f, 0.f, 0.f);
    float l0 = 0.f, l1 = 0.f;

    const uint32_t* M0 = g_Mb + (size_t)(b * SS + qr) * NT + split * NSPLIT;
    const uint32_t* M1 = M0 + (size_t)8 * NT;
    const uint4* Kg = (const uint4*)g_K + (size_t)b * SS * 8;
    const uint4* Vg = (const uint4*)g_V + (size_t)b * DD * 512;

    stage_tile(pbase,        ptid, split * NSPLIT + 0, Kg, Vg); CP_COMMIT();
    stage_tile(pbase + 8192, ptid, split * NSPLIT + 1, Kg, Vg); CP_COMMIT();

    uint32_t w0 = M0[0], w1 = M1[0];           // mask word pipeline

    for (int j = 0; j < NSPLIT; j++) {
        const char* cur = psm + (j & 1) * 8192;

        uint32_t wn0 = 0, wn1 = 0;
        if (j + 1 < NSPLIT) { wn0 = __ldg(&M0[j + 1]); wn1 = __ldg(&M1[j + 1]); }

        CP_WAIT1();
        BARP(1 + split);

        // ---- S = Q_rn * K_rn ----
        float4 S[4];
        #pragma unroll
        for (int n = 0; n < 4; n++) S[n] = make_float4(0.f, 0.f, 0.f, 0.f);
        #pragma unroll
        for (int kc = 0; kc < 4; kc++) {
            #pragma unroll
            for (int n = 0; n < 4; n++) {
                uint32_t cb = (lq + kc * 8) * 4;
                const char* base = cur + (n * 8 + gr) * 128 + (cb & 15);
                uint32_t b0 = *(const uint32_t*)(base + (((cb >> 4) ^ gr) << 4));
                uint32_t b1 = *(const uint32_t*)(base + ((((cb >> 4) + 1) ^ gr) << 4));
                mma16816(S[n], Ah[kc], b0, b1);
            }
        }

        // ---- mask + exp (ex2.approx, folded 0.125*log2e) ----
        #pragma unroll
        for (int n = 0; n < 4; n++) {
            int sh = n * 8 + lq * 2;
            S[n].x = ((w0 >> sh) & 1u)       ? 0.f : ex2a(S[n].x * SCL);
            S[n].y = ((w0 >> (sh + 1)) & 1u) ? 0.f : ex2a(S[n].y * SCL);
            S[n].z = ((w1 >> sh) & 1u)       ? 0.f : ex2a(S[n].z * SCL);
            S[n].w = ((w1 >> (sh + 1)) & 1u) ? 0.f : ex2a(S[n].w * SCL);
            l0 += S[n].x + S[n].y;
            l1 += S[n].z + S[n].w;
        }
        w0 = wn0; w1 = wn1;

        // ---- O += P_f16 * V_f16 (single term) ----
        #pragma unroll
        for (int kc = 0; kc < 2; kc++) {
            float4 pa = S[2 * kc], pb = S[2 * kc + 1];
            uint32_t Ph[4] = {rnh(pa.x, pa.y), rnh(pa.z, pa.w),
                              rnh(pb.x, pb.y), rnh(pb.z, pb.w)};
            #pragma unroll
            for (int n = 0; n < 8; n++) {
                uint32_t cb = (lq + kc * 8) * 4;
                const char* base = cur + 4096 + (n * 8 + gr) * 64 + (cb & 15);
                uint32_t v0 = *(const uint32_t*)(base + (((cb >> 4) ^ (gr >> 1)) << 4));
                uint32_t v1 = *(const uint32_t*)(base + ((((cb >> 4) + 1) ^ (gr >> 1)) << 4));
                mma16816h(O[n], Ph, v0, v1);
            }
        }

        BARP(1 + split);
        if (j + 2 < NSPLIT)
            stage_tile(pbase + (j & 1) * 8192, ptid, split * NSPLIT + j + 2, Kg, Vg);
        CP_COMMIT();
    }

    // ---- quad-reduce row sums ----
    l0 += __shfl_xor_sync(0xFFFFFFFFu, l0, 1);
    l0 += __shfl_xor_sync(0xFFFFFFFFu, l0, 2);
    l1 += __shfl_xor_sync(0xFFFFFFFFu, l1, 1);
    l1 += __shfl_xor_sync(0xFFFFFFFFu, l1, 2);

    // ---- combine the two k-splits via smem ----
    __syncthreads();                     // all buffers dead now
    float* cO = (float*)sm;              // 32 x 64 f32 = 8KB
    float* cL = (float*)(sm + 8192);     // 32 f32
    if (split == 1) {
        #pragma unroll
        for (int n = 0; n < 8; n++) {
            int c = n * 8 + lq * 2;
            cO[qloc * 64 + c]           = O[n].x;
            cO[qloc * 64 + c + 1]       = O[n].y;
            cO[(qloc + 8) * 64 + c]     = O[n].z;
            cO[(qloc + 8) * 64 + c + 1] = O[n].w;
        }
        if (lq == 0) { cL[qloc] = l0; cL[qloc + 8] = l1; }
    }
    __syncthreads();
    if (split == 0) {
        const float inv0 = 1.0f / (l0 + cL[qloc]);
        const float inv1 = 1.0f / (l1 + cL[qloc + 8]);
        float* o0 = out + (size_t)(b * SS + qr) * DD;
        float* o1 = o0 + (size_t)8 * DD;
        #pragma unroll
        for (int n = 0; n < 8; n++) {
            int c = n * 8 + lq * 2;
            *(float2*)&o0[c] = make_float2((O[n].x + cO[qloc * 64 + c]) * inv0,
                                           (O[n].y + cO[qloc * 64 + c + 1]) * inv0);
            *(float2*)&o1[c] = make_float2((O[n].z + cO[(qloc + 8) * 64 + c]) * inv1,
                                           (O[n].w + cO[(qloc + 8) * 64 + c + 1]) * inv1);
        }
    }
}

// ---------------------------------------------------------------------------
extern "C" void kernel_launch(void* const* d_in, const int* in_sizes, int n_in,
                              void* d_out, int out_size)
{
    const float* queries = (const float*)d_in[0];
    const float* keys    = (const float*)d_in[1];
    const float* values  = (const float*)d_in[2];
    const int*   mask    = (const int*)d_in[3];
    const float* W_q = (const float*)d_in[4];
    const float* W_k = (const float*)d_in[5];
    const float* W_v = (const float*)d_in[6];

    prep_kernel<<<896, 256>>>(queries, keys, values, W_q, W_k, W_v, mask);
    attn_kernel<<<dim3(SS / 32, BB), 128>>>((float*)d_out);
}

// round 14
// speedup vs baseline: 1.7676x; 1.1513x over previous
#include <cuda_runtime.h>
#include <cstdint>

#define BB 4
#define SS 4096
#define EE 1024
#define DD 64
#define TK 32
#define NT (SS / TK)      // 128 key tiles total
#define NSPLIT 64         // tiles per k-split

// ---------------- device scratch ----------------
__device__ uint32_t g_Q [BB * SS * DD / 2];   // [s][d] rounded bf16 pairs
__device__ uint32_t g_K [BB * SS * DD / 2];   // [s][d] rounded bf16 pairs
__device__ uint32_t g_V [BB * DD * SS / 2];   // [d][s] fp16 pairs (V^T)

// ---------------- helpers ----------------
__device__ __forceinline__ uint32_t hip(float a, float b) {
    return __byte_perm(__float_as_uint(a), __float_as_uint(b), 0x7632);
}
__device__ __forceinline__ float lof(float a) {
    return a - __uint_as_float(__float_as_uint(a) & 0xFFFF0000u);
}
__device__ __forceinline__ uint32_t lop(float a, float b) {
    uint32_t r;
    asm("cvt.rn.bf16x2.f32 %0, %1, %2;" : "=r"(r) : "f"(lof(b)), "f"(lof(a)));
    return r;
}
__device__ __forceinline__ uint32_t rnp(float a, float b) {   // bf16 pair
    uint32_t r;
    asm("cvt.rn.bf16x2.f32 %0, %1, %2;" : "=r"(r) : "f"(b), "f"(a));
    return r;
}
__device__ __forceinline__ uint32_t rnh(float a, float b) {   // fp16 pair
    uint32_t r;
    asm("cvt.rn.f16x2.f32 %0, %1, %2;" : "=r"(r) : "f"(b), "f"(a));
    return r;
}
__device__ __forceinline__ unsigned short f2h(float f) {
    unsigned short u; asm("cvt.rn.f16.f32 %0, %1;" : "=h"(u) : "f"(f)); return u;
}
__device__ __forceinline__ float ex2a(float x) {
    float r; asm("ex2.approx.f32 %0, %1;" : "=f"(r) : "f"(x)); return r;
}
#define SCL 0.18033688011112042f   /* 0.125 * log2(e) */
__device__ __forceinline__ void mma16816(float4& c, const uint32_t a[4],
                                         uint32_t b0, uint32_t b1) {
    asm volatile(
        "mma.sync.aligned.m16n8k16.row.col.f32.bf16.bf16.f32 "
        "{%0,%1,%2,%3}, {%4,%5,%6,%7}, {%8,%9}, {%0,%1,%2,%3};"
        : "+f"(c.x), "+f"(c.y), "+f"(c.z), "+f"(c.w)
        : "r"(a[0]), "r"(a[1]), "r"(a[2]), "r"(a[3]), "r"(b0), "r"(b1));
}
__device__ __forceinline__ void mma16816h(float4& c, const uint32_t a[4],
                                          uint32_t b0, uint32_t b1) {
    asm volatile(
        "mma.sync.aligned.m16n8k16.row.col.f32.f16.f16.f32 "
        "{%0,%1,%2,%3}, {%4,%5,%6,%7}, {%8,%9}, {%0,%1,%2,%3};"
        : "+f"(c.x), "+f"(c.y), "+f"(c.z), "+f"(c.w)
        : "r"(a[0]), "r"(a[1]), "r"(a[2]), "r"(a[3]), "r"(b0), "r"(b1));
}
__device__ __forceinline__ uint32_t smem_u32(const void* p) {
    uint32_t a;
    asm("{ .reg .u64 t; cvta.to.shared.u64 t, %1; cvt.u32.u64 %0, t; }" : "=r"(a) : "l"(p));
    return a;
}
__device__ __forceinline__ void cpa(uint32_t dst, const void* src) {
    asm volatile("cp.async.cg.shared.global [%0], [%1], 16;" :: "r"(dst), "l"(src));
}
#define CP_COMMIT() asm volatile("cp.async.commit_group;" ::: "memory")
#define CP_WAIT1()  asm volatile("cp.async.wait_group 1;" ::: "memory")
#define BARP(id)    asm volatile("bar.sync %0, 64;" :: "r"(id) : "memory")

#define RSTRIDE 144   // proj smem row stride

// ---------------------------------------------------------------------------
// Prep = projection only now (384 CTAs x 256 thr).
// py = bx/128: 0=Q rn, 1=K rn ([s][d] bf16), 2=V^T fp16 ([d][s]).
// ---------------------------------------------------------------------------
__global__ __launch_bounds__(256) void prep_kernel(
    const float* __restrict__ Xq, const float* __restrict__ Xk,
    const float* __restrict__ Xv,
    const float* __restrict__ Wq, const float* __restrict__ Wk,
    const float* __restrict__ Wv)
{
    const int tid = threadIdx.x;
    const int w = tid >> 5, l = tid & 31;

    const int px = blockIdx.x & 127;
    const int py = blockIdx.x >> 7;      // 0=Q, 1=K, 2=V

    const float* __restrict__ X;
    const float* __restrict__ W;
    if (py == 0)      { X = Xq; W = Wq; }
    else if (py == 1) { X = Xk; W = Wk; }
    else              { X = Xv; W = Wv; }

    __shared__ __align__(16) char sWh[64 * RSTRIDE];
    __shared__ __align__(16) char sWl[64 * RSTRIDE];

    const int gr = l >> 2, lq = l & 3;
    const int r0 = px * 128;

    float4 C[8];
    #pragma unroll
    for (int n = 0; n < 8; n++) C[n] = make_float4(0.f, 0.f, 0.f, 0.f);

    for (int e0 = 0; e0 < EE; e0 += 64) {
        __syncthreads();
        #pragma unroll
        for (int i = 0; i < 4; i++) {
            int idx = tid + i * 256;
            int d = idx >> 4, c4 = idx & 15;
            float4 wv = *(const float4*)&W[(size_t)d * EE + e0 + c4 * 4];
            *(uint2*)(sWh + d * RSTRIDE + c4 * 8) = make_uint2(hip(wv.x, wv.y), hip(wv.z, wv.w));
            *(uint2*)(sWl + d * RSTRIDE + c4 * 8) = make_uint2(lop(wv.x, wv.y), lop(wv.z, wv.w));
        }
        __syncthreads();

        const float* Xw = X + (size_t)(r0 + w * 16) * EE + e0;
        #pragma unroll
        for (int kc = 0; kc < 4; kc++) {
            float2 x00 = *(const float2*)&Xw[gr * EE + lq * 2 + kc * 16];
            float2 x10 = *(const float2*)&Xw[(gr + 8) * EE + lq * 2 + kc * 16];
            float2 x01 = *(const float2*)&Xw[gr * EE + lq * 2 + kc * 16 + 8];
            float2 x11 = *(const float2*)&Xw[(gr + 8) * EE + lq * 2 + kc * 16 + 8];
            uint32_t Ah[4] = {hip(x00.x, x00.y), hip(x10.x, x10.y),
                              hip(x01.x, x01.y), hip(x11.x, x11.y)};
            uint32_t Al[4] = {lop(x00.x, x00.y), lop(x10.x, x10.y),
                              lop(x01.x, x01.y), lop(x11.x, x11.y)};
            #pragma unroll
            for (int n = 0; n < 8; n++) {
                const char* bh = sWh + (n * 8 + gr) * RSTRIDE + (lq + kc * 8) * 4;
                const char* bl = sWl + (n * 8 + gr) * RSTRIDE + (lq + kc * 8) * 4;
                uint32_t bh0 = *(const uint32_t*)bh;
                uint32_t bh1 = *(const uint32_t*)(bh + 16);
                uint32_t bl0 = *(const uint32_t*)bl;
                uint32_t bl1 = *(const uint32_t*)(bl + 16);
                mma16816(C[n], Ah, bh0, bh1);
                mma16816(C[n], Al, bh0, bh1);
                mma16816(C[n], Ah, bl0, bl1);
            }
        }
    }

    const int r = r0 + w * 16 + gr;
    if (py < 2) {
        uint32_t* T = (py == 0) ? g_Q : g_K;
        #pragma unroll
        for (int n = 0; n < 8; n++) {
            int d2 = n * 4 + lq;
            T[(size_t)r * 32 + d2]       = rnp(C[n].x, C[n].y);
            T[(size_t)(r + 8) * 32 + d2] = rnp(C[n].z, C[n].w);
        }
    } else {
        unsigned short* V16 = (unsigned short*)g_V;
        const int bi = r >> 12, s = r & 4095;
        #pragma unroll
        for (int n = 0; n < 8; n++) {
            int d = n * 8 + lq * 2;
            size_t o0 = (size_t)(bi * DD + d) * SS + s;
            size_t o1 = (size_t)(bi * DD + d + 1) * SS + s;
            V16[o0]     = f2h(C[n].x);
            V16[o1]     = f2h(C[n].y);
            V16[o0 + 8] = f2h(C[n].z);
            V16[o1 + 8] = f2h(C[n].w);
        }
    }
}

// ---------------------------------------------------------------------------
// Attention, split-K=2 in-CTA: 128 thr / 4 warps / 32 q rows.
// S = Q_rn * K_rn (bf16); O += P_f16 * V_f16. RAW mask staged per tile via
// cp.async (32 rows x 32 int = 4KB, XOR chunk swizzle) -- no pack pass.
// Buffer per split per stage: K 4KB | V 4KB | M 4KB = 12KB; x2 stages x2
// splits = 48KB smem. 4 CTAs/SM -> all 512 CTAs in one wave.
// ---------------------------------------------------------------------------
__device__ __forceinline__ void stage_tile(
    uint32_t base, int ptid, int t,
    const uint4* Kg, const uint4* Vg, const int* Mg)
{
    const int k0 = t * TK;
    #pragma unroll
    for (int j = 0; j < 4; j++) {       // K: 32 rows x 8 chunks (4KB)
        int idx = ptid + j * 64;
        int r = idx >> 3, c = idx & 7;
        uint32_t d = base + r * 128 + ((c ^ (r & 7)) << 4);
        cpa(d, Kg + (size_t)(k0 + r) * 8 + c);
    }
    #pragma unroll
    for (int j = 0; j < 4; j++) {       // V^T: 64 rows x 4 chunks (4KB)
        int idx = ptid + j * 64;
        int r = idx >> 2, c = idx & 3;
        uint32_t d = base + 4096 + r * 64 + ((c ^ ((r >> 1) & 3)) << 4);
        cpa(d, Vg + (size_t)r * 512 + (k0 >> 3) + c);
    }
    #pragma unroll
    for (int j = 0; j < 4; j++) {       // mask: 32 q-rows x 8 chunks (4KB)
        int idx = ptid + j * 64;
        int r = idx >> 3, c = idx & 7;
        uint32_t d = base + 8192 + r * 128 + ((c ^ (r & 7)) << 4);
        cpa(d, (const uint4*)(Mg + (size_t)r * SS + k0) + c);
    }
}

__global__ __launch_bounds__(128, 4) void attn_kernel(
    const int* __restrict__ mask, float* __restrict__ out)
{
    __shared__ __align__(16) char sm[49152];

    const int tid = threadIdx.x;
    const int w = tid >> 5, l = tid & 31;
    const int gr = l >> 2, lq = l & 3;
    const int split = w >> 1, sub = w & 1;
    const int ptid = tid & 63;
    const int b = blockIdx.y;
    const int qloc = sub * 16 + gr;
    const int qr = blockIdx.x * 32 + qloc;

    const uint32_t pbase = smem_u32(sm) + split * 24576;
    const char* psm = sm + split * 24576;

    // Q fragments (rounded bf16)
    uint32_t Ah[4][4];
    {
        const uint32_t* Qp = g_Q + (size_t)b * SS * 32;
        #pragma unroll
        for (int kc = 0; kc < 4; kc++) {
            int c0 = lq + kc * 8;
            Ah[kc][0] = Qp[(size_t)qr * 32 + c0];
            Ah[kc][1] = Qp[(size_t)(qr + 8) * 32 + c0];
            Ah[kc][2] = Qp[(size_t)qr * 32 + c0 + 4];
            Ah[kc][3] = Qp[(size_t)(qr + 8) * 32 + c0 + 4];
        }
    }

    float4 O[8];
    #pragma unroll
    for (int n = 0; n < 8; n++) O[n] = make_float4(0.f, 0.f, 0.f, 0.f);
    float l0 = 0.f, l1 = 0.f;

    const uint4* Kg = (const uint4*)g_K + (size_t)b * SS * 8;
    const uint4* Vg = (const uint4*)g_V + (size_t)b * DD * 512;
    const int* Mg = mask + ((size_t)(b * SS + blockIdx.x * 32)) * SS;

    stage_tile(pbase,         ptid, split * NSPLIT + 0, Kg, Vg, Mg); CP_COMMIT();
    stage_tile(pbase + 12288, ptid, split * NSPLIT + 1, Kg, Vg, Mg); CP_COMMIT();

    for (int j = 0; j < NSPLIT; j++) {
        const char* cur = psm + (j & 1) * 12288;

        CP_WAIT1();
        BARP(1 + split);

        // ---- S = Q_rn * K_rn ----
        float4 S[4];
        #pragma unroll
        for (int n = 0; n < 4; n++) S[n] = make_float4(0.f, 0.f, 0.f, 0.f);
        #pragma unroll
        for (int kc = 0; kc < 4; kc++) {
            #pragma unroll
            for (int n = 0; n < 4; n++) {
                uint32_t cb = (lq + kc * 8) * 4;
                const char* base = cur + (n * 8 + gr) * 128 + (cb & 15);
                uint32_t b0 = *(const uint32_t*)(base + (((cb >> 4) ^ gr) << 4));
                uint32_t b1 = *(const uint32_t*)(base + ((((cb >> 4) + 1) ^ gr) << 4));
                mma16816(S[n], Ah[kc], b0, b1);
            }
        }

        // ---- mask (raw ints from smem) + exp ----
        const char* mbuf = cur + 8192;
        #pragma unroll
        for (int n = 0; n < 4; n++) {
            uint32_t coff = (uint32_t)((((2 * n + (lq >> 1)) ^ gr) << 4) + (lq & 1) * 8);
            int2 ma = *(const int2*)(mbuf + qloc * 128 + coff);
            int2 mb = *(const int2*)(mbuf + (qloc + 8) * 128 + coff);
            S[n].x = ma.x ? 0.f : ex2a(S[n].x * SCL);
            S[n].y = ma.y ? 0.f : ex2a(S[n].y * SCL);
            S[n].z = mb.x ? 0.f : ex2a(S[n].z * SCL);
            S[n].w = mb.y ? 0.f : ex2a(S[n].w * SCL);
            l0 += S[n].x + S[n].y;
            l1 += S[n].z + S[n].w;
        }

        // ---- O += P_f16 * V_f16 ----
        #pragma unroll
        for (int kc = 0; kc < 2; kc++) {
            float4 pa = S[2 * kc], pb = S[2 * kc + 1];
            uint32_t Ph[4] = {rnh(pa.x, pa.y), rnh(pa.z, pa.w),
                              rnh(pb.x, pb.y), rnh(pb.z, pb.w)};
            #pragma unroll
            for (int n = 0; n < 8; n++) {
                uint32_t cb = (lq + kc * 8) * 4;
                const char* base = cur + 4096 + (n * 8 + gr) * 64 + (cb & 15);
                uint32_t v0 = *(const uint32_t*)(base + (((cb >> 4) ^ (gr >> 1)) << 4));
                uint32_t v1 = *(const uint32_t*)(base + ((((cb >> 4) + 1) ^ (gr >> 1)) << 4));
                mma16816h(O[n], Ph, v0, v1);
            }
        }

        BARP(1 + split);
        if (j + 2 < NSPLIT)
            stage_tile(pbase + (j & 1) * 12288, ptid, split * NSPLIT + j + 2,
                       Kg, Vg, Mg);
        CP_COMMIT();
    }

    // ---- quad-reduce row sums ----
    l0 += __shfl_xor_sync(0xFFFFFFFFu, l0, 1);
    l0 += __shfl_xor_sync(0xFFFFFFFFu, l0, 2);
    l1 += __shfl_xor_sync(0xFFFFFFFFu, l1, 1);
    l1 += __shfl_xor_sync(0xFFFFFFFFu, l1, 2);

    // ---- combine the two k-splits via smem ----
    __syncthreads();                     // all buffers dead now
    float* cO = (float*)sm;              // 32 x 64 f32 = 8KB
    float* cL = (float*)(sm + 8192);     // 32 f32
    if (split == 1) {
        #pragma unroll
        for (int n = 0; n < 8; n++) {
            int c = n * 8 + lq * 2;
            cO[qloc * 64 + c]           = O[n].x;
            cO[qloc * 64 + c + 1]       = O[n].y;
            cO[(qloc + 8) * 64 + c]     = O[n].z;
            cO[(qloc + 8) * 64 + c + 1] = O[n].w;
        }
        if (lq == 0) { cL[qloc] = l0; cL[qloc + 8] = l1; }
    }
    __syncthreads();
    if (split == 0) {
        const float inv0 = 1.0f / (l0 + cL[qloc]);
        const float inv1 = 1.0f / (l1 + cL[qloc + 8]);
        float* o0 = out + (size_t)(b * SS + qr) * DD;
        float* o1 = o0 + (size_t)8 * DD;
        #pragma unroll
        for (int n = 0; n < 8; n++) {
            int c = n * 8 + lq * 2;
            *(float2*)&o0[c] = make_float2((O[n].x + cO[qloc * 64 + c]) * inv0,
                                           (O[n].y + cO[qloc * 64 + c + 1]) * inv0);
            *(float2*)&o1[c] = make_float2((O[n].z + cO[(qloc + 8) * 64 + c]) * inv1,
                                           (O[n].w + cO[(qloc + 8) * 64 + c + 1]) * inv1);
        }
    }
}

// ---------------------------------------------------------------------------
extern "C" void kernel_launch(void* const* d_in, const int* in_sizes, int n_in,
                              void* d_out, int out_size)
{
    const float* queries = (const float*)d_in[0];
    const float* keys    = (const float*)d_in[1];
    const float* values  = (const float*)d_in[2];
    const int*   mask    = (const int*)d_in[3];
    const float* W_q = (const float*)d_in[4];
    const float* W_k = (const float*)d_in[5];
    const float* W_v = (const float*)d_in[6];

    prep_kernel<<<384, 256>>>(queries, keys, values, W_q, W_k, W_v);
    attn_kernel<<<dim3(SS / 32, BB), 128>>>(mask, (float*)d_out);
}